// round 1
// baseline (speedup 1.0000x reference)
#include <cuda_runtime.h>
#include <cstdint>

typedef unsigned long long u64;

// ---------- f32x2 / MUFU helpers ----------
__device__ __forceinline__ u64 ffma2(u64 a, u64 b, u64 c) {
    u64 d;
    asm("fma.rn.f32x2 %0, %1, %2, %3;" : "=l"(d) : "l"(a), "l"(b), "l"(c));
    return d;
}
__device__ __forceinline__ u64 fpack(float x, float y) {
    u64 d;
    asm("mov.b64 %0, {%1, %2};" : "=l"(d) : "r"(__float_as_uint(x)), "r"(__float_as_uint(y)));
    return d;
}
__device__ __forceinline__ u64 fdup(float s) { return fpack(s, s); }
__device__ __forceinline__ void funpack(u64 v, float& x, float& y) {
    unsigned int a, b;
    asm("mov.b64 {%0, %1}, %2;" : "=r"(a), "=r"(b) : "l"(v));
    x = __uint_as_float(a);
    y = __uint_as_float(b);
}
__device__ __forceinline__ float fex2(float x) {
    float r; asm("ex2.approx.f32 %0, %1;" : "=f"(r) : "f"(x)); return r;
}
__device__ __forceinline__ float frcp(float x) {
    float r; asm("rcp.approx.f32 %0, %1;" : "=f"(r) : "f"(x)); return r;
}
__device__ __forceinline__ float fsig(float x) {
    return frcp(1.0f + fex2(-1.44269504f * x));
}
__device__ __forceinline__ float ftanh_(float x) {
    // tanh(x) = 1 - 2/(1 + exp(2x)) ; exp(2x) = ex2(2.885390x)
    return fmaf(-2.0f, frcp(1.0f + fex2(2.88539008f * x)), 1.0f);
}

// ---------- problem constants ----------
constexpr int BATCH = 8192;
constexpr int HID   = 10;
constexpr int STEPS = 512;
constexpr int PAIRS = BATCH / 2;              // 4096
constexpr int WARPS_NEEDED = (PAIRS + 2) / 3; // 1366
constexpr int WPB = 8;
constexpr int TPB = WPB * 32;                 // 256
constexpr int GRID = (WARPS_NEEDED + WPB - 1) / WPB; // 171

// Folded weights: G = w_ih @ l2_w @ l1_w (30x10), d = w_ih@l2_b + (w_ih@l2_w)@l1_b + b_ih (30)
__device__ float g_G[300];
__device__ float g_d[30];

// ---------- prep kernel: fold the input path ----------
__global__ void prep_kernel(const float* __restrict__ w_ih,
                            const float* __restrict__ b_ih,
                            const float* __restrict__ l1_w,
                            const float* __restrict__ l1_b,
                            const float* __restrict__ l2_w,
                            const float* __restrict__ l2_b) {
    __shared__ float Wm[300]; // w_ih @ l2_w : (30,10)
    int t = threadIdx.x;
    if (t < 300) {
        int r = t / 10, m = t % 10;
        float s = 0.0f;
        for (int i = 0; i < 64; i++) s += w_ih[r * 64 + i] * l2_w[i * 10 + m];
        Wm[t] = s;
    }
    __syncthreads();
    if (t < 300) {
        int r = t / 10, k = t % 10;
        float g = 0.0f;
        for (int m = 0; m < 10; m++) g += Wm[r * 10 + m] * l1_w[m * 10 + k];
        g_G[t] = g;
    } else if (t < 330) {
        int r = t - 300;
        float s = b_ih[r];
        for (int i = 0; i < 64; i++) s += w_ih[r * 64 + i] * l2_b[i];
        for (int m = 0; m < 10; m++) s += Wm[r * 10 + m] * l1_b[m];
        g_d[r] = s;
    }
}

// ---------- main recurrence kernel ----------
// thread = (batch-pair, gate dim j). 3 pairs per warp on lanes 0..29.
// Two batch elements per thread packed into f32x2. h exchanged through a
// warp-local double-buffered shared array; one __syncwarp per step.
__global__ void __launch_bounds__(TPB) gru_kernel(
    const float* __restrict__ hidden,
    const float* __restrict__ w_hh,
    const float* __restrict__ b_ih,
    const float* __restrict__ b_hh,
    const float* __restrict__ l1_w,
    const float* __restrict__ l1_b,
    float* __restrict__ out) {
    __shared__ u64 hsh[WPB][2][4][HID];

    const int lane = threadIdx.x & 31;
    const int w    = threadIdx.x >> 5;
    const int p    = lane / 10;        // 0..2 real pairs, 3 = spare lanes 30/31
    const int j    = lane - p * 10;    // 0..9
    const int wg   = blockIdx.x * WPB + w;
    const int pairIdx = wg * 3 + (p < 3 ? p : 0);
    const bool valid  = (p < 3) && (pairIdx < PAIRS);
    const int bb      = valid ? pairIdx * 2 : 0;

    // per-thread folded weight rows, duplicated into both f32x2 halves
    u64 Mr[10], Mz[10], Gn[10], Wn[10], L1[10];
#pragma unroll
    for (int k = 0; k < 10; k++) {
        Mr[k] = fdup(w_hh[j * 10 + k]        + g_G[j * 10 + k]);
        Mz[k] = fdup(w_hh[(10 + j) * 10 + k] + g_G[(10 + j) * 10 + k]);
        Gn[k] = fdup(g_G[(20 + j) * 10 + k]);
        Wn[k] = fdup(w_hh[(20 + j) * 10 + k]);
        L1[k] = fdup(l1_w[j * 10 + k]);
    }
    const float br  = b_hh[j]      + g_d[j];
    const float bz  = b_hh[10 + j] + g_d[10 + j];
    const float bin = g_d[20 + j];
    const float bhn = b_hh[20 + j];

    float hx = hidden[bb * 10 + j];
    float hy = hidden[(bb + 1) * 10 + j];

    hsh[w][0][p][j] = fpack(hx, hy);
    __syncwarp();

    // peeled step 0: x0 = 0 -> gi = b_ih exactly (no G·h term)
    {
        float aRx = b_hh[j] + b_ih[j];
        float aZx = b_hh[10 + j] + b_ih[10 + j];
        float aRy = aRx, aZy = aZx;
        float aHx = bhn, aHy = bhn;
#pragma unroll
        for (int k = 0; k < 10; k++) {
            float kx, ky;
            funpack(hsh[w][0][p][k], kx, ky);
            float wr = w_hh[j * 10 + k];
            float wz = w_hh[(10 + j) * 10 + k];
            float wn = w_hh[(20 + j) * 10 + k];
            aRx = fmaf(wr, kx, aRx); aRy = fmaf(wr, ky, aRy);
            aZx = fmaf(wz, kx, aZx); aZy = fmaf(wz, ky, aZy);
            aHx = fmaf(wn, kx, aHx); aHy = fmaf(wn, ky, aHy);
        }
        float inb = b_ih[20 + j];
        float rx = fsig(aRx), ry = fsig(aRy);
        float zx = fsig(aZx), zy = fsig(aZy);
        float nx = ftanh_(fmaf(rx, aHx, inb));
        float ny = ftanh_(fmaf(ry, aHy, inb));
        hx = fmaf(zx, hx - nx, nx);
        hy = fmaf(zy, hy - ny, ny);
    }
    hsh[w][1][p][j] = fpack(hx, hy);

    const u64 vbr = fdup(br), vbz = fdup(bz), vbin = fdup(bin),
              vbhn = fdup(bhn), vl1b = fdup(l1_b[j]);

    // REVERSE output: o_t goes to row (511 - t); at iter t we emit o_{t-1} -> row 512 - t
    float* o0 = out + (size_t)bb * (STEPS * HID) + (STEPS - 1) * HID + j;
    float* o1 = out + (size_t)(bb + 1) * (STEPS * HID) + (STEPS - 1) * HID + j;

#pragma unroll 2
    for (int t = 1; t < STEPS; ++t) {
        __syncwarp();
        const int rb = t & 1;
        u64 aR = vbr, aZ = vbz, aIN = vbin, aHN = vbhn, aO = vl1b;
#pragma unroll
        for (int k = 0; k < 10; k++) {
            u64 hk = hsh[w][rb][p][k];
            aR  = ffma2(Mr[k], hk, aR);
            aZ  = ffma2(Mz[k], hk, aZ);
            aIN = ffma2(Gn[k], hk, aIN);
            aHN = ffma2(Wn[k], hk, aHN);
            aO  = ffma2(L1[k], hk, aO);
        }
        // o_{t-1} = L1·h_new(t-1) + l1_b  (hk above IS h_new(t-1))
        float ox, oy;
        funpack(aO, ox, oy);
        if (valid) { *o0 = ox; *o1 = oy; }
        o0 -= HID; o1 -= HID;

        float aRx, aRy, aZx, aZy, aIx, aIy, aHx, aHy;
        funpack(aR, aRx, aRy); funpack(aZ, aZx, aZy);
        funpack(aIN, aIx, aIy); funpack(aHN, aHx, aHy);
        float rx = fsig(aRx), ry = fsig(aRy);
        float zx = fsig(aZx), zy = fsig(aZy);
        float nx = ftanh_(fmaf(rx, aHx, aIx));
        float ny = ftanh_(fmaf(ry, aHy, aIy));
        hx = fmaf(zx, hx - nx, nx);
        hy = fmaf(zy, hy - ny, ny);
        hsh[w][rb ^ 1][p][j] = fpack(hx, hy);
    }

    // epilogue: o_511 -> row 0 (h_new(511) sits in buffer 0 after t=511)
    __syncwarp();
    {
        u64 aO = vl1b;
#pragma unroll
        for (int k = 0; k < 10; k++) aO = ffma2(L1[k], hsh[w][0][p][k], aO);
        float ox, oy;
        funpack(aO, ox, oy);
        if (valid) { *o0 = ox; *o1 = oy; }
    }
}

extern "C" void kernel_launch(void* const* d_in, const int* in_sizes, int n_in,
                              void* d_out, int out_size) {
    const float* hidden = (const float*)d_in[0];
    const float* w_ih   = (const float*)d_in[1];
    const float* w_hh   = (const float*)d_in[2];
    const float* b_ih   = (const float*)d_in[3];
    const float* b_hh   = (const float*)d_in[4];
    const float* l1_w   = (const float*)d_in[5];
    const float* l1_b   = (const float*)d_in[6];
    const float* l2_w   = (const float*)d_in[7];
    const float* l2_b   = (const float*)d_in[8];
    // d_in[9] = step (constant 512, folded at compile time)

    prep_kernel<<<1, 384>>>(w_ih, b_ih, l1_w, l1_b, l2_w, l2_b);
    gru_kernel<<<GRID, TPB>>>(hidden, w_hh, b_ih, b_hh, l1_w, l1_b, (float*)d_out);
}

// round 2
// speedup vs baseline: 1.2121x; 1.2121x over previous
#include <cuda_runtime.h>
#include <cstdint>

typedef unsigned long long u64;

// ---------- f32x2 / MUFU helpers ----------
__device__ __forceinline__ u64 ffma2(u64 a, u64 b, u64 c) {
    u64 d;
    asm("fma.rn.f32x2 %0, %1, %2, %3;" : "=l"(d) : "l"(a), "l"(b), "l"(c));
    return d;
}
__device__ __forceinline__ u64 fadd2(u64 a, u64 b) {
    u64 d;
    asm("add.rn.f32x2 %0, %1, %2;" : "=l"(d) : "l"(a), "l"(b));
    return d;
}
__device__ __forceinline__ u64 fpack(float x, float y) {
    u64 d;
    asm("mov.b64 %0, {%1, %2};" : "=l"(d) : "r"(__float_as_uint(x)), "r"(__float_as_uint(y)));
    return d;
}
__device__ __forceinline__ u64 fdup(float s) { return fpack(s, s); }
__device__ __forceinline__ void funpack(u64 v, float& x, float& y) {
    unsigned int a, b;
    asm("mov.b64 {%0, %1}, %2;" : "=r"(a), "=r"(b) : "l"(v));
    x = __uint_as_float(a);
    y = __uint_as_float(b);
}
__device__ __forceinline__ float fex2(float x) {
    float r; asm("ex2.approx.f32 %0, %1;" : "=f"(r) : "f"(x)); return r;
}
__device__ __forceinline__ float frcp(float x) {
    float r; asm("rcp.approx.f32 %0, %1;" : "=f"(r) : "f"(x)); return r;
}
__device__ __forceinline__ float ftanha(float x) {
    float r; asm("tanh.approx.f32 %0, %1;" : "=f"(r) : "f"(x)); return r;
}
__device__ __forceinline__ float fsig_exact(float x) {
    return frcp(1.0f + fex2(-1.44269504f * x));
}
__device__ __forceinline__ float ftanh_exact(float x) {
    return fmaf(-2.0f, frcp(1.0f + fex2(2.88539008f * x)), 1.0f);
}

// ---------- problem constants ----------
constexpr int BATCH = 8192;
constexpr int HID   = 10;
constexpr int STEPS = 512;
constexpr int PAIRS = BATCH / 2;              // 4096
constexpr int WARPS_NEEDED = (PAIRS + 2) / 3; // 1366
constexpr int WPB = 8;
constexpr int TPB = WPB * 32;                 // 256
constexpr int GRID = (WARPS_NEEDED + WPB - 1) / WPB; // 171

// 2*log2(e): fold into n-gate weights so tanh arg is ready for ex2 directly
#define CN 2.885390081777927f

// Folded weights: G = w_ih @ l2_w @ l1_w (30x10), d = w_ih@l2_b + (w_ih@l2_w)@l1_b + b_ih (30)
__device__ float g_G[300];
__device__ float g_d[30];

// ---------- prep kernel: fold the input path ----------
__global__ void prep_kernel(const float* __restrict__ w_ih,
                            const float* __restrict__ b_ih,
                            const float* __restrict__ l1_w,
                            const float* __restrict__ l1_b,
                            const float* __restrict__ l2_w,
                            const float* __restrict__ l2_b) {
    __shared__ float Wm[300]; // w_ih @ l2_w : (30,10)
    int t = threadIdx.x;
    if (t < 300) {
        int r = t / 10, m = t % 10;
        float s = 0.0f;
        for (int i = 0; i < 64; i++) s += w_ih[r * 64 + i] * l2_w[i * 10 + m];
        Wm[t] = s;
    }
    __syncthreads();
    if (t < 300) {
        int r = t / 10, k = t % 10;
        float g = 0.0f;
        for (int m = 0; m < 10; m++) g += Wm[r * 10 + m] * l1_w[m * 10 + k];
        g_G[t] = g;
    } else if (t < 330) {
        int r = t - 300;
        float s = b_ih[r];
        for (int i = 0; i < 64; i++) s += w_ih[r * 64 + i] * l2_b[i];
        for (int m = 0; m < 10; m++) s += Wm[r * 10 + m] * l1_b[m];
        g_d[r] = s;
    }
}

// ---------- main recurrence kernel ----------
// thread = (batch-pair, gate dim j). 3 pairs per warp on lanes 0..29.
// Two batch elements packed into f32x2. h exchanged through a warp-local
// double-buffered shared array; one __syncwarp per step.
// r/z gates: sigma(a) = 0.5 + 0.5*tanh(a/2), 0.5 folded into weights,
//            tanh.approx.f32 (1 MUFU).
// n gate: exact tanh via ex2/rcp, 2*log2e folded into weights.
__global__ void __launch_bounds__(TPB) gru_kernel(
    const float* __restrict__ hidden,
    const float* __restrict__ w_hh,
    const float* __restrict__ b_ih,
    const float* __restrict__ b_hh,
    const float* __restrict__ l1_w,
    const float* __restrict__ l1_b,
    float* __restrict__ out) {
    __shared__ u64 hsh[WPB][2][4][HID];

    const int lane = threadIdx.x & 31;
    const int w    = threadIdx.x >> 5;
    const int p    = lane / 10;        // 0..2 real pairs, 3 = spare lanes 30/31
    const int j    = lane - p * 10;    // 0..9
    const int wg   = blockIdx.x * WPB + w;
    const int pairIdx = wg * 3 + (p < 3 ? p : 0);
    const bool valid  = (p < 3) && (pairIdx < PAIRS);
    const int bb      = valid ? pairIdx * 2 : 0;

    // per-thread folded + scaled weight rows, duplicated into both f32x2 halves
    u64 Mr[10], Mz[10], Gn[10], Wn[10], L1[10];
#pragma unroll
    for (int k = 0; k < 10; k++) {
        Mr[k] = fdup(0.5f * (w_hh[j * 10 + k]        + g_G[j * 10 + k]));
        Mz[k] = fdup(0.5f * (w_hh[(10 + j) * 10 + k] + g_G[(10 + j) * 10 + k]));
        Gn[k] = fdup(CN * g_G[(20 + j) * 10 + k]);
        Wn[k] = fdup(CN * w_hh[(20 + j) * 10 + k]);
        L1[k] = fdup(l1_w[j * 10 + k]);
    }
    const u64 vbr  = fdup(0.5f * (b_hh[j]      + g_d[j]));
    const u64 vbz  = fdup(0.5f * (b_hh[10 + j] + g_d[10 + j]));
    const u64 vbin = fdup(CN * g_d[20 + j]);
    const u64 vbhn = fdup(CN * b_hh[20 + j]);
    const u64 vl1b = fdup(l1_b[j]);
    const u64 ZERO2 = 0ULL;
    const u64 HALF2 = fdup(0.5f);
    const u64 ONE2  = fdup(1.0f);
    const u64 NEG12 = fdup(-1.0f);
    const u64 NEG22 = fdup(-2.0f);

    float hx = hidden[bb * 10 + j];
    float hy = hidden[(bb + 1) * 10 + j];

    hsh[w][0][p][j] = fpack(hx, hy);
    __syncwarp();

    // peeled step 0: x0 = 0 -> gi = b_ih exactly (no G*h term). Exact activations.
    {
        float aRx = b_hh[j] + b_ih[j];
        float aZx = b_hh[10 + j] + b_ih[10 + j];
        float aRy = aRx, aZy = aZx;
        float aHx = b_hh[20 + j], aHy = aHx;
#pragma unroll
        for (int k = 0; k < 10; k++) {
            float kx, ky;
            funpack(hsh[w][0][p][k], kx, ky);
            float wr = w_hh[j * 10 + k];
            float wz = w_hh[(10 + j) * 10 + k];
            float wn = w_hh[(20 + j) * 10 + k];
            aRx = fmaf(wr, kx, aRx); aRy = fmaf(wr, ky, aRy);
            aZx = fmaf(wz, kx, aZx); aZy = fmaf(wz, ky, aZy);
            aHx = fmaf(wn, kx, aHx); aHy = fmaf(wn, ky, aHy);
        }
        float inb = b_ih[20 + j];
        float rx = fsig_exact(aRx), ry = fsig_exact(aRy);
        float zx = fsig_exact(aZx), zy = fsig_exact(aZy);
        float nx = ftanh_exact(fmaf(rx, aHx, inb));
        float ny = ftanh_exact(fmaf(ry, aHy, inb));
        hx = fmaf(zx, hx - nx, nx);
        hy = fmaf(zy, hy - ny, ny);
    }
    u64 hv = fpack(hx, hy);
    hsh[w][1][p][j] = hv;

    // REVERSE output: o_t -> row (511 - t); at iter t we emit o_{t-1} -> row 512 - t
    float* o0 = out + (size_t)bb * (STEPS * HID) + (STEPS - 1) * HID + j;
    float* o1 = out + (size_t)(bb + 1) * (STEPS * HID) + (STEPS - 1) * HID + j;

#pragma unroll 2
    for (int t = 1; t < STEPS; ++t) {
        __syncwarp();
        const int rb = t & 1;
        // split chains for the two critical accumulators (aR feeds r -> n path)
        u64 aR = vbr, aR2 = ZERO2;
        u64 aH = vbhn, aH2 = ZERO2;
        u64 aZ = vbz, aI = vbin, aO = vl1b;
#pragma unroll
        for (int k = 0; k < 10; k += 2) {
            u64 h0 = hsh[w][rb][p][k];
            u64 h1 = hsh[w][rb][p][k + 1];
            aR  = ffma2(Mr[k], h0, aR);   aR2 = ffma2(Mr[k + 1], h1, aR2);
            aH  = ffma2(Wn[k], h0, aH);   aH2 = ffma2(Wn[k + 1], h1, aH2);
            aZ  = ffma2(Mz[k], h0, aZ);   aZ  = ffma2(Mz[k + 1], h1, aZ);
            aI  = ffma2(Gn[k], h0, aI);   aI  = ffma2(Gn[k + 1], h1, aI);
            aO  = ffma2(L1[k], h0, aO);   aO  = ffma2(L1[k + 1], h1, aO);
        }
        aR = fadd2(aR, aR2);
        aH = fadd2(aH, aH2);

        // store o_{t-1} (aO computed from h_t which is h_new of step t-1)
        {
            float ox, oy;
            funpack(aO, ox, oy);
            if (valid) { *o0 = ox; *o1 = oy; }
            o0 -= HID; o1 -= HID;
        }

        // r = 0.5 + 0.5*tanh(aR)  (aR pre-scaled by 0.5)
        float aRx, aRy, aZx, aZy;
        funpack(aR, aRx, aRy);
        funpack(aZ, aZx, aZy);
        u64 rv = ffma2(HALF2, fpack(ftanha(aRx), ftanha(aRy)), HALF2);
        u64 zv = ffma2(HALF2, fpack(ftanha(aZx), ftanha(aZy)), HALF2);

        // n = tanh arg (pre-scaled by 2*log2e): arg = aI + r*aH
        u64 argv = ffma2(rv, aH, aI);
        float ax, ay;
        funpack(argv, ax, ay);
        float qx = frcp(1.0f + fex2(ax));
        float qy = frcp(1.0f + fex2(ay));
        u64 nv = ffma2(NEG22, fpack(qx, qy), ONE2);   // 1 - 2*q

        // h' = n + z*(h - n)
        u64 dv = ffma2(nv, NEG12, hv);                // h - n
        hv = ffma2(zv, dv, nv);
        hsh[w][rb ^ 1][p][j] = hv;
    }

    // epilogue: o_511 -> row 0 (h_512 sits in buffer 0 after t=511)
    __syncwarp();
    {
        u64 aO = vl1b;
#pragma unroll
        for (int k = 0; k < 10; k++) aO = ffma2(L1[k], hsh[w][0][p][k], aO);
        float ox, oy;
        funpack(aO, ox, oy);
        if (valid) { *o0 = ox; *o1 = oy; }
    }
}

extern "C" void kernel_launch(void* const* d_in, const int* in_sizes, int n_in,
                              void* d_out, int out_size) {
    const float* hidden = (const float*)d_in[0];
    const float* w_ih   = (const float*)d_in[1];
    const float* w_hh   = (const float*)d_in[2];
    const float* b_ih   = (const float*)d_in[3];
    const float* b_hh   = (const float*)d_in[4];
    const float* l1_w   = (const float*)d_in[5];
    const float* l1_b   = (const float*)d_in[6];
    const float* l2_w   = (const float*)d_in[7];
    const float* l2_b   = (const float*)d_in[8];

    prep_kernel<<<1, 384>>>(w_ih, b_ih, l1_w, l1_b, l2_w, l2_b);
    gru_kernel<<<GRID, TPB>>>(hidden, w_hh, b_ih, b_hh, l1_w, l1_b, (float*)d_out);
}

// round 3
// speedup vs baseline: 1.3038x; 1.0756x over previous
#include <cuda_runtime.h>
#include <cstdint>

typedef unsigned long long u64;

// ---------- f32x2 / MUFU helpers ----------
__device__ __forceinline__ u64 ffma2(u64 a, u64 b, u64 c) {
    u64 d;
    asm("fma.rn.f32x2 %0, %1, %2, %3;" : "=l"(d) : "l"(a), "l"(b), "l"(c));
    return d;
}
__device__ __forceinline__ u64 fadd2(u64 a, u64 b) {
    u64 d;
    asm("add.rn.f32x2 %0, %1, %2;" : "=l"(d) : "l"(a), "l"(b));
    return d;
}
__device__ __forceinline__ u64 fpack(float x, float y) {
    u64 d;
    asm("mov.b64 %0, {%1, %2};" : "=l"(d) : "r"(__float_as_uint(x)), "r"(__float_as_uint(y)));
    return d;
}
__device__ __forceinline__ u64 fdup(float s) { return fpack(s, s); }
__device__ __forceinline__ void funpack(u64 v, float& x, float& y) {
    unsigned int a, b;
    asm("mov.b64 {%0, %1}, %2;" : "=r"(a), "=r"(b) : "l"(v));
    x = __uint_as_float(a);
    y = __uint_as_float(b);
}
__device__ __forceinline__ float fex2(float x) {
    float r; asm("ex2.approx.f32 %0, %1;" : "=f"(r) : "f"(x)); return r;
}
__device__ __forceinline__ float frcp(float x) {
    float r; asm("rcp.approx.f32 %0, %1;" : "=f"(r) : "f"(x)); return r;
}
__device__ __forceinline__ float ftanha(float x) {
    float r; asm("tanh.approx.f32 %0, %1;" : "=f"(r) : "f"(x)); return r;
}
__device__ __forceinline__ float fsig_exact(float x) {
    return frcp(1.0f + fex2(-1.44269504f * x));
}
__device__ __forceinline__ float ftanh_exact(float x) {
    return fmaf(-2.0f, frcp(1.0f + fex2(2.88539008f * x)), 1.0f);
}

// ---------- problem constants ----------
constexpr int BATCH = 8192;
constexpr int HID   = 10;
constexpr int STEPS = 512;
constexpr int PAIRS = BATCH / 2;       // 4096
constexpr int WPB   = 10;
constexpr int TPB   = WPB * 32;        // 320
constexpr int GRID  = 148;             // exactly 1 block per SM
constexpr int TOTW  = GRID * WPB;      // 1480 warps; pair p_i = g + i*1480

// Folded weights: G = w_ih @ l2_w @ l1_w (30x10), d = w_ih@l2_b + (w_ih@l2_w)@l1_b + b_ih (30)
__device__ float g_G[300];
__device__ float g_d[30];
// sink rows for lanes without a valid batch pair (branch-free stores)
__device__ float g_sink[2 * STEPS * HID];

// ---------- prep kernel: fold the input path ----------
__global__ void prep_kernel(const float* __restrict__ w_ih,
                            const float* __restrict__ b_ih,
                            const float* __restrict__ l1_w,
                            const float* __restrict__ l1_b,
                            const float* __restrict__ l2_w,
                            const float* __restrict__ l2_b) {
    __shared__ float Wm[300]; // w_ih @ l2_w : (30,10)
    int t = threadIdx.x;
    if (t < 300) {
        int r = t / 10, m = t % 10;
        float s = 0.0f;
        for (int i = 0; i < 64; i++) s += w_ih[r * 64 + i] * l2_w[i * 10 + m];
        Wm[t] = s;
    }
    __syncthreads();
    if (t < 300) {
        int r = t / 10, k = t % 10;
        float g = 0.0f;
        for (int m = 0; m < 10; m++) g += Wm[r * 10 + m] * l1_w[m * 10 + k];
        g_G[t] = g;
    } else if (t < 330) {
        int r = t - 300;
        float s = b_ih[r];
        for (int i = 0; i < 64; i++) s += w_ih[r * 64 + i] * l2_b[i];
        for (int m = 0; m < 10; m++) s += Wm[r * 10 + m] * l1_b[m];
        g_d[r] = s;
    }
}

// ---------- main recurrence kernel ----------
// thread = (batch-pair, gate dim j). 3 pairs per warp on lanes 0..29, pairs
// assigned round-robin across 1480 warps so every warp runs the identical
// instruction stream and every SM gets exactly one 10-warp block.
// Two batch elements packed into f32x2; h exchanged through a warp-local
// double-buffered shared array (LDS.128 reads); one __syncwarp per step.
// All three activations via tanh.approx (sigma(a)=0.5+0.5*tanh(a/2), the 0.5
// folded into r/z weights).
__global__ void __launch_bounds__(TPB) gru_kernel(
    const float* __restrict__ hidden,
    const float* __restrict__ w_hh,
    const float* __restrict__ b_ih,
    const float* __restrict__ b_hh,
    const float* __restrict__ l1_w,
    const float* __restrict__ l1_b,
    float* __restrict__ out) {
    __shared__ alignas(16) u64 hsh[WPB][2][4][HID];

    const int lane = threadIdx.x & 31;
    const int w    = threadIdx.x >> 5;
    const int p    = lane / 10;        // 0..2 real pairs, 3 = spare lanes 30/31
    const int j    = lane - p * 10;    // 0..9
    const int g    = blockIdx.x * WPB + w;
    const int pairIdx = g + (p < 3 ? p : 0) * TOTW;   // round-robin pair map
    const bool valid  = (p < 3) && (pairIdx < PAIRS);
    const int bb      = valid ? pairIdx * 2 : 0;

    // per-thread folded + scaled weight rows, duplicated into both f32x2 halves
    u64 Mr[10], Mz[10], Gn[10], Wn[10], L1[10];
#pragma unroll
    for (int k = 0; k < 10; k++) {
        Mr[k] = fdup(0.5f * (w_hh[j * 10 + k]        + g_G[j * 10 + k]));
        Mz[k] = fdup(0.5f * (w_hh[(10 + j) * 10 + k] + g_G[(10 + j) * 10 + k]));
        Gn[k] = fdup(g_G[(20 + j) * 10 + k]);
        Wn[k] = fdup(w_hh[(20 + j) * 10 + k]);
        L1[k] = fdup(l1_w[j * 10 + k]);
    }
    const u64 vbr  = fdup(0.5f * (b_hh[j]      + g_d[j]));
    const u64 vbz  = fdup(0.5f * (b_hh[10 + j] + g_d[10 + j]));
    const u64 vbin = fdup(g_d[20 + j]);
    const u64 vbhn = fdup(b_hh[20 + j]);
    const u64 vl1b = fdup(l1_b[j]);
    const u64 ZERO2 = 0ULL;
    const u64 HALF2 = fdup(0.5f);
    const u64 NEG12 = fdup(-1.0f);

    float hx = hidden[bb * 10 + j];
    float hy = hidden[(bb + 1) * 10 + j];

    // zero the spare slot so LDS.128 of slot 3 never reads garbage
    if (p == 0) { hsh[w][0][3][j] = 0ULL; hsh[w][1][3][j] = 0ULL; }
    hsh[w][0][p][j] = fpack(hx, hy);
    __syncwarp();

    // peeled step 0: x0 = 0 -> gi = b_ih exactly (no G*h term). Exact activations.
    {
        float aRx = b_hh[j] + b_ih[j];
        float aZx = b_hh[10 + j] + b_ih[10 + j];
        float aRy = aRx, aZy = aZx;
        float aHx = b_hh[20 + j], aHy = aHx;
#pragma unroll
        for (int k = 0; k < 10; k++) {
            float kx, ky;
            funpack(hsh[w][0][p][k], kx, ky);
            float wr = w_hh[j * 10 + k];
            float wz = w_hh[(10 + j) * 10 + k];
            float wn = w_hh[(20 + j) * 10 + k];
            aRx = fmaf(wr, kx, aRx); aRy = fmaf(wr, ky, aRy);
            aZx = fmaf(wz, kx, aZx); aZy = fmaf(wz, ky, aZy);
            aHx = fmaf(wn, kx, aHx); aHy = fmaf(wn, ky, aHy);
        }
        float inb = b_ih[20 + j];
        float rx = fsig_exact(aRx), ry = fsig_exact(aRy);
        float zx = fsig_exact(aZx), zy = fsig_exact(aZy);
        float nx = ftanh_exact(fmaf(rx, aHx, inb));
        float ny = ftanh_exact(fmaf(ry, aHy, inb));
        hx = fmaf(zx, hx - nx, nx);
        hy = fmaf(zy, hy - ny, ny);
    }
    u64 hv = fpack(hx, hy);
    hsh[w][1][p][j] = hv;

    // REVERSE output: o_t -> row (511 - t); at iter t we emit o_{t-1} -> row 512 - t
    // invalid lanes walk a sink row instead (branch-free stores, in-bounds)
    float* o0;
    float* o1;
    if (valid) {
        o0 = out + (size_t)bb * (STEPS * HID) + (STEPS - 1) * HID + j;
        o1 = out + (size_t)(bb + 1) * (STEPS * HID) + (STEPS - 1) * HID + j;
    } else {
        o0 = g_sink + (STEPS - 1) * HID + j;
        o1 = g_sink + STEPS * HID + (STEPS - 1) * HID + j;
    }

#pragma unroll 2
    for (int t = 1; t < STEPS; ++t) {
        __syncwarp();
        const int rb = t & 1;
        const ulonglong2* hp = reinterpret_cast<const ulonglong2*>(&hsh[w][rb][p][0]);
        // split chains for the two accumulators on the serial path
        u64 aR = vbr, aR2 = ZERO2;
        u64 aH = vbhn, aH2 = ZERO2;
        u64 aZ = vbz, aI = vbin, aO = vl1b;
#pragma unroll
        for (int kk = 0; kk < 5; kk++) {
            const ulonglong2 hh = hp[kk];           // LDS.128: h[2kk], h[2kk+1]
            const int k = 2 * kk;
            aR  = ffma2(Mr[k], hh.x, aR);   aR2 = ffma2(Mr[k + 1], hh.y, aR2);
            aH  = ffma2(Wn[k], hh.x, aH);   aH2 = ffma2(Wn[k + 1], hh.y, aH2);
            aZ  = ffma2(Mz[k], hh.x, aZ);   aZ  = ffma2(Mz[k + 1], hh.y, aZ);
            aI  = ffma2(Gn[k], hh.x, aI);   aI  = ffma2(Gn[k + 1], hh.y, aI);
            aO  = ffma2(L1[k], hh.x, aO);   aO  = ffma2(L1[k + 1], hh.y, aO);
        }
        aR = fadd2(aR, aR2);
        aH = fadd2(aH, aH2);

        // store o_{t-1} (aO computed from h_t which is h_new of step t-1)
        {
            float ox, oy;
            funpack(aO, ox, oy);
            *o0 = ox; *o1 = oy;
            o0 -= HID; o1 -= HID;
        }

        // r = 0.5 + 0.5*tanh(aR), z likewise (aR/aZ pre-scaled by 0.5)
        float aRx, aRy, aZx, aZy;
        funpack(aR, aRx, aRy);
        funpack(aZ, aZx, aZy);
        u64 rv = ffma2(HALF2, fpack(ftanha(aRx), ftanha(aRy)), HALF2);
        u64 zv = ffma2(HALF2, fpack(ftanha(aZx), ftanha(aZy)), HALF2);

        // n = tanh(aI + r*aH)
        u64 argv = ffma2(rv, aH, aI);
        float ax, ay;
        funpack(argv, ax, ay);
        u64 nv = fpack(ftanha(ax), ftanha(ay));

        // h' = n + z*(h - n)
        u64 dv = ffma2(nv, NEG12, hv);
        hv = ffma2(zv, dv, nv);
        hsh[w][rb ^ 1][p][j] = hv;
    }

    // epilogue: o_511 -> row 0 (h_512 sits in buffer 0 after t=511)
    __syncwarp();
    {
        u64 aO = vl1b;
#pragma unroll
        for (int k = 0; k < 10; k++) aO = ffma2(L1[k], hsh[w][0][p][k], aO);
        float ox, oy;
        funpack(aO, ox, oy);
        *o0 = ox; *o1 = oy;
    }
}

extern "C" void kernel_launch(void* const* d_in, const int* in_sizes, int n_in,
                              void* d_out, int out_size) {
    const float* hidden = (const float*)d_in[0];
    const float* w_ih   = (const float*)d_in[1];
    const float* w_hh   = (const float*)d_in[2];
    const float* b_ih   = (const float*)d_in[3];
    const float* b_hh   = (const float*)d_in[4];
    const float* l1_w   = (const float*)d_in[5];
    const float* l1_b   = (const float*)d_in[6];
    const float* l2_w   = (const float*)d_in[7];
    const float* l2_b   = (const float*)d_in[8];

    prep_kernel<<<1, 384>>>(w_ih, b_ih, l1_w, l1_b, l2_w, l2_b);
    gru_kernel<<<GRID, TPB>>>(hidden, w_hh, b_ih, b_hh, l1_w, l1_b, (float*)d_out);
}